// round 17
// baseline (speedup 1.0000x reference)
#include <cuda_runtime.h>
#include <cuda_bf16.h>

#define HID 32
#define CUTOFF_SQ 6.25f
#define GRID 148          // == SM count: all blocks co-resident -> spin barrier safe
#define THREADS 512
#define NWARPS (THREADS / 32)
#define TBL 2048
#define NMAX 4096

__device__ float2 g_tbl2[TBL + 1];   // entry k: ( e(k), e(k+1) )  over u = r^2
__device__ float4 g_pos[NMAX];
__device__ int    g_bar1;            // zero-init at load; reset each call
__device__ int    g_bar2;

__global__ __launch_bounds__(THREADS)
void fused_kernel(const float* __restrict__ xyz,
                  const float* __restrict__ cell_diag,
                  const float* __restrict__ W1,
                  const float* __restrict__ b1,
                  const float* __restrict__ W2,
                  const float* __restrict__ b2,
                  float* __restrict__ out,
                  int n)
{
    __shared__ float warp_sums[NWARPS];

    const int tid  = threadIdx.x;
    const int lane = tid & 31;
    const int wid  = tid >> 5;
    const int gtid = blockIdx.x * THREADS + tid;

    if (gtid == 0) out[0] = 0.0f;

    // ---- phase 1a: pack coords to float4 ----
    if (gtid < n) {
        g_pos[gtid] = make_float4(xyz[3 * gtid + 0], xyz[3 * gtid + 1],
                                  xyz[3 * gtid + 2], 0.0f);
    }

    // ---- phase 1b: energy table, one warp per entry (lane = hidden unit) ----
    const int entry = blockIdx.x * NWARPS + wid;   // 148*16 = 2368 warps >= TBL+1
    if (entry <= TBL) {
        const float du = CUTOFF_SQ / (float)TBL;
        float w1v = W1[lane], b1v = b1[lane], w2v = W2[lane];
        float r0 = sqrtf(du * (float)entry);
        float r1 = sqrtf(du * (float)(entry + 1));
        float v0 = w2v * tanhf(fmaf(r0, w1v, b1v));
        float v1 = w2v * tanhf(fmaf(r1, w1v, b1v));
        #pragma unroll
        for (int off = 16; off > 0; off >>= 1) {
            v0 += __shfl_xor_sync(0xFFFFFFFFu, v0, off);
            v1 += __shfl_xor_sync(0xFFFFFFFFu, v1, off);
        }
        if (lane == 0) {
            float b2v = b2[0];
            g_tbl2[entry] = make_float2(v0 + b2v, v1 + b2v);
        }
    }

    // ---- grid barrier (arrive + spin; all blocks resident by construction) ----
    __threadfence();
    __syncthreads();
    if (tid == 0) {
        atomicAdd(&g_bar1, 1);
        while (atomicAdd(&g_bar1, 0) < GRID) __nanosleep(64);
    }
    __syncthreads();

    // ---- phase 2: triangular pairs, rows interleaved across blocks ----
    const float Lx = cell_diag[0], Ly = cell_diag[1], Lz = cell_diag[2];
    const float iLx = 1.0f / Lx, iLy = 1.0f / Ly, iLz = 1.0f / Lz;
    const float invDr2 = (float)TBL / CUTOFF_SQ;
    const float r2clamp = CUTOFF_SQ * (1.0f - 1.0f / (float)TBL);  // k <= TBL-1

    float acc = 0.0f;
    for (int i = blockIdx.x; i < n - 1; i += GRID) {
        const float4 pi = g_pos[i];
        for (int j = i + 1 + tid; j < n; j += THREADS) {
            float4 pj = g_pos[j];
            float dx = pj.x - pi.x;
            float dy = pj.y - pi.y;
            float dz = pj.z - pi.z;

            // min image: equivalent to reference offset rule for d in (-L, L)
            dx = fmaf(rintf(dx * iLx), -Lx, dx);
            dy = fmaf(rintf(dy * iLy), -Ly, dy);
            dz = fmaf(rintf(dz * iLz), -Lz, dz);

            float r2 = fmaf(dx, dx, fmaf(dy, dy, dz * dz));

            bool hit = (r2 < CUTOFF_SQ) && (r2 > 0.0f);

            float t = fminf(r2, r2clamp) * invDr2;
            int k = (int)t;
            float f = t - (float)k;
            float2 e01 = g_tbl2[k];                  // one LDG.64
            acc += hit ? fmaf(f, e01.y - e01.x, e01.x) : 0.0f;
        }
    }

    // ---- block reduce + one atomic per block ----
    #pragma unroll
    for (int off = 16; off > 0; off >>= 1)
        acc += __shfl_down_sync(0xFFFFFFFFu, acc, off);
    if (lane == 0) warp_sums[wid] = acc;
    __syncthreads();
    if (wid == 0) {
        float v = (lane < NWARPS) ? warp_sums[lane] : 0.0f;
        #pragma unroll
        for (int off = 16; off > 0; off >>= 1)
            v += __shfl_down_sync(0xFFFFFFFFu, v, off);
        if (lane == 0) atomicAdd(out, v);
    }

    // ---- exit: last block to arrive resets both counters (replay-safe) ----
    __syncthreads();
    if (tid == 0) {
        int prev = atomicAdd(&g_bar2, 1);
        if (prev == GRID - 1) {
            atomicExch(&g_bar1, 0);
            atomicExch(&g_bar2, 0);
        }
    }
}

extern "C" void kernel_launch(void* const* d_in, const int* in_sizes, int n_in,
                              void* d_out, int out_size) {
    const float* xyz       = (const float*)d_in[0];
    const float* cell_diag = (const float*)d_in[1];
    const float* W1        = (const float*)d_in[2];
    const float* b1        = (const float*)d_in[3];
    const float* W2        = (const float*)d_in[4];
    const float* b2        = (const float*)d_in[5];
    float* out = (float*)d_out;

    int n = in_sizes[0] / 3;

    fused_kernel<<<GRID, THREADS>>>(xyz, cell_diag, W1, b1, W2, b2, out, n);
}